// round 4
// baseline (speedup 1.0000x reference)
#include <cuda_runtime.h>
#include <cstdint>

// ---------------------------------------------------------------------------
// SpikingClassifier on GB300 — Round 3 (fp32 SIMT + Kahan, flip-noise hardened)
//
// W_lat = c*(ones-eye) + d*eye (c,d read from device mem)
//   => I_lat[b,j] = c*(S_b - v[b,j]) + d*v[b,j],  S_b = rowsum(v_h[b,:])
// GEMMs: two-level accumulation (16-term FMA tile partials + packed Kahan
// carry) => near-exact fp32 sums. Elementwise ops use unfused __f*_rn
// intrinsics to replicate XLA's mul/add rounding exactly.
// ---------------------------------------------------------------------------

namespace {
constexpr int kB    = 2048;
constexpr int kNIn  = 4096;
constexpr int kNHid = 4096;
constexpr int kNCls = 1024;
constexpr int kSteps = 5;
constexpr float kTau = 0.8f;
constexpr float kOmt = 0.2f;   // float32(1.0 - 0.8) == 0.2f
constexpr float kVth = 0.5f;
}

__device__ float g_Iin[(size_t)kB * kNHid];
__device__ float g_vh [(size_t)kB * kNHid];
__device__ float g_hsp[(size_t)kB * kNHid];
__device__ float g_vo [(size_t)kB * kNCls];
__device__ float g_cnt[(size_t)kB * kNCls];

using u64 = unsigned long long;

__device__ __forceinline__ u64 ffma2(u64 a, u64 b, u64 c) {
    u64 d;
    asm("fma.rn.f32x2 %0, %1, %2, %3;" : "=l"(d) : "l"(a), "l"(b), "l"(c));
    return d;
}
__device__ __forceinline__ u64 fadd2(u64 a, u64 b) {
    u64 d;
    asm("add.rn.f32x2 %0, %1, %2;" : "=l"(d) : "l"(a), "l"(b));
    return d;
}
__device__ __forceinline__ u64 pack_dup(float x) {
    u64 d;
    asm("mov.b64 %0, {%1, %1};" : "=l"(d) : "r"(__float_as_uint(x)));
    return d;
}
__device__ __forceinline__ u64 pack2(float lo, float hi) {
    u64 d;
    asm("mov.b64 %0, {%1, %2};" : "=l"(d) : "r"(__float_as_uint(lo)), "r"(__float_as_uint(hi)));
    return d;
}
__device__ __forceinline__ float lo32(u64 v) { return __uint_as_float((unsigned)(v & 0xffffffffull)); }
__device__ __forceinline__ float hi32(u64 v) { return __uint_as_float((unsigned)(v >> 32)); }

constexpr int BM = 128, BN = 64, BK = 16;
constexpr int LDA = 132;   // padded row stride (floats), 16B-aligned rows
constexpr int LDB = 68;

// C[M,N] = A[M,K] @ B[N,K]^T (+bias in epilogue). Row-major, K contiguous.
// Per-thread microtile: 8 M (as 4 packed pairs) x 4 N.
// MODE 0: Cout = acc + bias
// MODE 1: fused output-neuron LIF (v_o, spike, counts)
// MODE 2: Cout = cnt/5 + 0.5*(acc+bias); RELU_A applies relu on A loads.
template<bool RELU_A, int MODE>
__global__ __launch_bounds__(256, 1)
void gemm_nt(const float* __restrict__ A, const float* __restrict__ Bw,
             const float* __restrict__ bias,
             float* __restrict__ Cout,
             float* __restrict__ vo, float* __restrict__ cnt,
             int N, int K, int t)
{
    __shared__ float As[BK][LDA];
    __shared__ float Bs[BK][LDB];

    const int tid = threadIdx.x;
    const int tx  = tid & 15;        // n:  tx*4
    const int ty  = tid >> 4;        // m:  ty*8
    const int m0  = blockIdx.y * BM;
    const int n0  = blockIdx.x * BN;

    const int lr = tid >> 2;         // 0..63
    const int lc = (tid & 3) << 2;   // 0,4,8,12

    const float* Ag = A  + (size_t)(m0 + lr) * K + lc;
    const float* Bg = Bw + (size_t)(n0 + lr) * K + lc;

    const u64 M1 = pack2(-1.0f, -1.0f);

    u64 s[4][4], cc[4][4];           // Kahan running sum + carry; [m-pair][n]
    #pragma unroll
    for (int i = 0; i < 4; i++)
        #pragma unroll
        for (int j = 0; j < 4; j++) { s[i][j] = 0ull; cc[i][j] = 0ull; }

    for (int k0 = 0; k0 < K; k0 += BK) {
        // --- load A tile (128x16) transposed, 2 float4 per thread ---
        #pragma unroll
        for (int p = 0; p < 2; p++) {
            float4 va = *reinterpret_cast<const float4*>(Ag + (size_t)(p * 64) * K + k0);
            if (RELU_A) {
                va.x = fmaxf(va.x, 0.f); va.y = fmaxf(va.y, 0.f);
                va.z = fmaxf(va.z, 0.f); va.w = fmaxf(va.w, 0.f);
            }
            const int r = lr + p * 64;
            As[lc + 0][r] = va.x; As[lc + 1][r] = va.y;
            As[lc + 2][r] = va.z; As[lc + 3][r] = va.w;
        }
        // --- load B tile (64x16) transposed, 1 float4 per thread ---
        {
            float4 vb = *reinterpret_cast<const float4*>(Bg + k0);
            Bs[lc + 0][lr] = vb.x; Bs[lc + 1][lr] = vb.y;
            Bs[lc + 2][lr] = vb.z; Bs[lc + 3][lr] = vb.w;
        }
        __syncthreads();

        // --- tile partial: fresh accumulators, 16-term FMA chains ---
        u64 tp[4][4];
        #pragma unroll
        for (int i = 0; i < 4; i++)
            #pragma unroll
            for (int j = 0; j < 4; j++) tp[i][j] = 0ull;

        #pragma unroll
        for (int kk = 0; kk < BK; kk++) {
            float4 a0 = *reinterpret_cast<const float4*>(&As[kk][ty * 8]);
            float4 a1 = *reinterpret_cast<const float4*>(&As[kk][ty * 8 + 4]);
            float4 b  = *reinterpret_cast<const float4*>(&Bs[kk][tx * 4]);
            u64 ap[4];
            ap[0] = pack2(a0.x, a0.y);
            ap[1] = pack2(a0.z, a0.w);
            ap[2] = pack2(a1.x, a1.y);
            ap[3] = pack2(a1.z, a1.w);
            u64 bd[4];
            bd[0] = pack_dup(b.x); bd[1] = pack_dup(b.y);
            bd[2] = pack_dup(b.z); bd[3] = pack_dup(b.w);
            #pragma unroll
            for (int i = 0; i < 4; i++)
                #pragma unroll
                for (int j = 0; j < 4; j++)
                    tp[i][j] = ffma2(ap[i], bd[j], tp[i][j]);
        }

        // --- Kahan fold: y = tp - c; tnew = s + y; c = (tnew - s) - y; s = tnew ---
        #pragma unroll
        for (int i = 0; i < 4; i++)
            #pragma unroll
            for (int j = 0; j < 4; j++) {
                u64 y  = ffma2(cc[i][j], M1, tp[i][j]);   // tp - c
                u64 tn = fadd2(s[i][j], y);
                u64 z  = ffma2(s[i][j], M1, tn);          // tn - s
                cc[i][j] = ffma2(y, M1, z);               // z - y
                s[i][j]  = tn;
            }
        __syncthreads();
    }

    // final correction: s += c
    #pragma unroll
    for (int i = 0; i < 4; i++)
        #pragma unroll
        for (int j = 0; j < 4; j++) s[i][j] = fadd2(s[i][j], cc[i][j]);

    // --- epilogue (unfused fp32 to mirror XLA's mul/add rounding) ---
    #pragma unroll
    for (int i = 0; i < 4; i++) {
        const int m = m0 + ty * 8 + i * 2;     // pair (m, m+1)
        #pragma unroll
        for (int j = 0; j < 4; j++) {
            const int n = n0 + tx * 4 + j;
            const float bn = bias[n];
            const float c0 = __fadd_rn(lo32(s[i][j]), bn);
            const float c1 = __fadd_rn(hi32(s[i][j]), bn);
            const size_t i0 = (size_t)m * N + n;
            const size_t i1 = i0 + (size_t)N;
            if constexpr (MODE == 0) {
                Cout[i0] = c0;
                Cout[i1] = c1;
            } else if constexpr (MODE == 1) {
                #pragma unroll
                for (int h = 0; h < 2; h++) {
                    const size_t idx = h ? i1 : i0;
                    const float Io = h ? c1 : c0;
                    const float vold = (t == 0) ? 0.f : vo[idx];
                    const float vn = __fadd_rn(__fmul_rn(kTau, vold),
                                               __fmul_rn(kOmt, Io));
                    const bool sp = (vn >= kVth);
                    const float cold = (t == 0) ? 0.f : cnt[idx];
                    vo[idx]  = sp ? 0.f : vn;
                    cnt[idx] = sp ? __fadd_rn(cold, 1.0f) : cold;
                }
            } else {
                #pragma unroll
                for (int h = 0; h < 2; h++) {
                    const size_t idx = h ? i1 : i0;
                    const float an = h ? c1 : c0;
                    const float lg = __fdiv_rn(cnt[idx], 5.0f);
                    Cout[idx] = __fadd_rn(lg, __fmul_rn(0.5f, an));
                }
            }
        }
    }
}

// Hidden-layer LIF step: S_b = rowsum(v_h) (Kahan + tree), then update.
__global__ __launch_bounds__(256)
void hidden_update(const float* __restrict__ Iin, float* __restrict__ vh,
                   float* __restrict__ hsp, const float* __restrict__ Wlat, int t)
{
    __shared__ float red[256];
    const int b   = blockIdx.x;
    const int tid = threadIdx.x;
    const float dlat = Wlat[0];   // diagonal
    const float clat = Wlat[1];   // off-diagonal
    const size_t base = (size_t)b * kNHid;

    float v[16];
    float sum = 0.f, carry = 0.f;
    #pragma unroll
    for (int e = 0; e < 16; e++) {
        const float vv = (t == 0) ? 0.f : vh[base + e * 256 + tid];
        v[e] = vv;
        // Kahan
        const float y  = __fsub_rn(vv, carry);
        const float tn = __fadd_rn(sum, y);
        carry = __fsub_rn(__fsub_rn(tn, sum), y);
        sum = tn;
    }
    red[tid] = __fadd_rn(sum, carry);
    __syncthreads();
    #pragma unroll
    for (int off = 128; off > 0; off >>= 1) {
        if (tid < off) red[tid] = __fadd_rn(red[tid], red[tid + off]);
        __syncthreads();
    }
    const float S = red[0];

    #pragma unroll
    for (int e = 0; e < 16; e++) {
        const size_t idx = base + e * 256 + tid;
        const float Il = __fadd_rn(__fmul_rn(clat, __fsub_rn(S, v[e])),
                                   __fmul_rn(dlat, v[e]));
        const float tsum = __fadd_rn(Iin[idx], Il);
        const float vn = __fadd_rn(__fmul_rn(kTau, v[e]),
                                   __fmul_rn(kOmt, tsum));
        const bool sp = (vn >= kVth);
        vh[idx]  = sp ? 0.f : vn;
        hsp[idx] = sp ? 1.f : 0.f;
    }
}

extern "C" void kernel_launch(void* const* d_in, const int* in_sizes, int n_in,
                              void* d_out, int out_size)
{
    const float* x     = (const float*)d_in[0];
    const float* Winw  = (const float*)d_in[1];
    const float* Winb  = (const float*)d_in[2];
    const float* Woutw = (const float*)d_in[3];
    const float* Woutb = (const float*)d_in[4];
    const float* Wlat  = (const float*)d_in[5];
    float* out = (float*)d_out;

    float *pIin, *pvh, *phsp, *pvo, *pcnt;
    cudaGetSymbolAddress((void**)&pIin, g_Iin);
    cudaGetSymbolAddress((void**)&pvh,  g_vh);
    cudaGetSymbolAddress((void**)&phsp, g_hsp);
    cudaGetSymbolAddress((void**)&pvo,  g_vo);
    cudaGetSymbolAddress((void**)&pcnt, g_cnt);

    // I_in = x @ W_in^T + b_in
    gemm_nt<false, 0><<<dim3(kNHid / BN, kB / BM), 256>>>(
        x, Winw, Winb, pIin, nullptr, nullptr, kNHid, kNIn, 0);

    for (int t = 0; t < kSteps; t++) {
        hidden_update<<<kB, 256>>>(pIin, pvh, phsp, Wlat, t);
        gemm_nt<false, 1><<<dim3(kNCls / BN, kB / BM), 256>>>(
            phsp, Woutw, Woutb, nullptr, pvo, pcnt, kNCls, kNHid, t);
    }

    // out = counts/5 + 0.5 * (relu(I_in) @ W_out^T + b_out)
    gemm_nt<true, 2><<<dim3(kNCls / BN, kB / BM), 256>>>(
        pIin, Woutw, Woutb, out, nullptr, pcnt, kNCls, kNHid, 0);
}